// round 15
// baseline (speedup 1.0000x reference)
#include <cuda_runtime.h>
#include <cuda_fp16.h>
#include <cstdint>

// ---------------------------------------------------------------------------
// GCN, 4 layers + heads. R15 = R14 base + issue-bound agg optimized:
//  ncu showed k_agg at 66.9% issue (not bytes-bound). Cut instructions/edge:
//  - pairwise __hadd2 combine of edge pairs before widening to fp32
//  - g_esrc read as int4 (warp-uniform LDG.128) after scalar align prologue
// ---------------------------------------------------------------------------

constexpr int NN = 50000;
constexpr int NE = 800000;

__device__ int    g_outdeg[NN];
__device__ int    g_indeg[NN];
__device__ float  g_nsrc[NN];
__device__ float  g_ndst[NN];
__device__ int    g_rowptr[NN + 1];
__device__ int    g_cursor[NN];
__device__ int    g_esrc[NE];
__device__ uint2  g_hs[(size_t)NN * 32];    // fp16 activations (gather source)
__device__ uint2  g_agg[(size_t)NN * 32];   // fp16 aggregated * norm_dst (GEMM A)
__device__ __half g_whT[3][128 * 128];      // W0..W2 fp16 transposed [n][k]
__device__ float2 g_zz[NN];                 // (z, z2) per node
__device__ float  g_q[128];                 // W3 @ Wp
__device__ float  g_q2[128];                // W3 @ Wv
__device__ float  g_cPI;

__device__ __forceinline__ void mma_f16(float* c, const uint32_t* a,
                                        uint32_t b0, uint32_t b1) {
    asm("mma.sync.aligned.m16n8k16.row.col.f32.f16.f16.f32 "
        "{%0,%1,%2,%3},{%4,%5,%6,%7},{%8,%9},{%0,%1,%2,%3};"
        : "+f"(c[0]), "+f"(c[1]), "+f"(c[2]), "+f"(c[3])
        : "r"(a[0]), "r"(a[1]), "r"(a[2]), "r"(a[3]), "r"(b0), "r"(b1));
}

__device__ __forceinline__ uint2 pack4h(float4 v) {
    uint2 r;
    __half2 h0 = __floats2half2_rn(v.x, v.y);
    __half2 h1 = __floats2half2_rn(v.z, v.w);
    r.x = *(uint32_t*)&h0;
    r.y = *(uint32_t*)&h1;
    return r;
}
__device__ __forceinline__ float4 unpack4h(uint2 u) {
    __half2 h0 = *(__half2*)&u.x;
    __half2 h1 = *(__half2*)&u.y;
    float2 f0 = __half22float2(h0);
    float2 f1 = __half22float2(h1);
    return make_float4(f0.x, f0.y, f1.x, f1.y);
}

// --------------------------- setup ----------------------------------------

constexpr int HIST_BLOCKS = (NE + 255) / 256;       // 3125
constexpr int PREP_BLOCKS = 1 + 192;                // heads + W convert

__global__ void k_histprep(const int* __restrict__ src, const int* __restrict__ dst,
                           const float* __restrict__ W0, const float* __restrict__ W1,
                           const float* __restrict__ W2,
                           const float* __restrict__ W3, const float* __restrict__ b3,
                           const float* __restrict__ Wp, const float* __restrict__ bp,
                           const float* __restrict__ Wv, const float* __restrict__ bv,
                           float* __restrict__ out) {
    int gb = blockIdx.x;
    if (gb < HIST_BLOCKS) {
        int e = gb * 256 + threadIdx.x;
        if (e < NE) {
            atomicAdd(&g_outdeg[src[e]], 1);
            atomicAdd(&g_indeg[dst[e]], 1);
        }
    } else if (gb == HIST_BLOCKS) {
        int k = threadIdx.x;
        if (k < 128) {
            float a = 0.f, c = 0.f;
            for (int j = 0; j < 64; j++) {
                float w = W3[k * 64 + j];
                a += w * Wp[j];
                c += w * Wv[j];
            }
            g_q[k] = a;
            g_q2[k] = c;
            if (k == 0) {
                float cp = 0.f, cv = 0.f;
                for (int j = 0; j < 64; j++) { cp += b3[j] * Wp[j]; cv += b3[j] * Wv[j]; }
                g_cPI = cp + bp[0];
                out[NN] = (float)NN * cv + bv[0];
            }
        }
    } else {
        int idx = (gb - HIST_BLOCKS - 1) * 256 + threadIdx.x;   // 0 .. 3*16384-1
        if (idx < 3 * 16384) {
            int layer = idx >> 14;
            int rem = idx & 16383;
            int k = rem >> 7;
            int n = rem & 127;
            const float* W = (layer == 0) ? W0 : (layer == 1) ? W1 : W2;
            g_whT[layer][n * 128 + k] = __float2half(W[k * 128 + n]);
        }
    }
}

// Single-block scan only.
__global__ void k_scan() {
    constexpr int CH = (NN + 1023) / 1024;   // 49
    __shared__ int ts[1024];
    int t = threadIdx.x;
    int base = t * CH;
    int s = 0;
    for (int i = 0; i < CH; i++) {
        int idx = base + i;
        int v = (idx < NN) ? g_indeg[idx] : 0;
        if (idx < NN) g_rowptr[idx] = s;
        s += v;
    }
    ts[t] = s;
    __syncthreads();
    for (int off = 1; off < 1024; off <<= 1) {
        int v = (t >= off) ? ts[t - off] : 0;
        __syncthreads();
        ts[t] += v;
        __syncthreads();
    }
    int offset = ts[t] - s;
    for (int i = 0; i < CH; i++) {
        int idx = base + i;
        if (idx < NN) {
            int p = g_rowptr[idx] + offset;
            g_rowptr[idx] = p;
            g_cursor[idx] = p;
        }
    }
    if (t == 1023) g_rowptr[NN] = ts[1023];
}

constexpr int FILL_BLOCKS = (NE + 255) / 256;            // 3125
constexpr int NORM_BLOCKS = (NN + 255) / 256;            // 196
constexpr int SC0_BLOCKS  = (NN * 32 + 255) / 256;       // 6250

__global__ void k_fillnormscale(const int* __restrict__ src, const int* __restrict__ dst,
                                const float* __restrict__ feats) {
    int gb = blockIdx.x;
    if (gb < FILL_BLOCKS) {
        int e = gb * 256 + threadIdx.x;
        if (e < NE) {
            int p = atomicAdd(&g_cursor[dst[e]], 1);
            g_esrc[p] = src[e];
        }
    } else if (gb < FILL_BLOCKS + NORM_BLOCKS) {
        int j = (gb - FILL_BLOCKS) * 256 + threadIdx.x;
        if (j < NN) {
            g_nsrc[j] = rsqrtf((float)max(g_outdeg[j], 1));
            g_ndst[j] = rsqrtf((float)max(g_indeg[j], 1));
        }
    } else {
        int j = (gb - FILL_BLOCKS - NORM_BLOCKS) * 256 + threadIdx.x;  // uint2 idx
        if (j < NN * 32) {
            int node = j >> 5;
            float s = rsqrtf((float)max(g_outdeg[node], 1));
            float4 x = ((const float4*)feats)[j];
            x.x *= s; x.y *= s; x.z *= s; x.w *= s;
            g_hs[j] = pack4h(x);
        }
    }
}

// --------------------------- aggregation ----------------------------------
// One warp per node; lane owns 4 feats (8B fp16). Issue-count optimized:
// edge pairs combined with __hadd2 before widening; esrc read via int4.

__global__ void k_agg() {
    int v = blockIdx.x * (blockDim.x >> 5) + (threadIdx.x >> 5);
    if (v >= NN) return;
    int lane = threadIdx.x & 31;
    int beg = g_rowptr[v], end = g_rowptr[v + 1];
    float2 a0 = make_float2(0.f, 0.f), a1 = make_float2(0.f, 0.f);
    float2 b0 = make_float2(0.f, 0.f), b1 = make_float2(0.f, 0.f);
    int e = beg;

    // scalar prologue to 16B-align e for int4 esrc reads
    for (; e < end && (e & 3); e++) {
        float4 f = unpack4h(g_hs[(size_t)g_esrc[e] * 32 + lane]);
        a0.x += f.x; a0.y += f.y; b0.x += f.z; b0.y += f.w;
    }
    for (; e + 7 < end; e += 8) {
        int4 e0 = *(const int4*)&g_esrc[e];
        int4 e1 = *(const int4*)&g_esrc[e + 4];
        uint2 x0 = g_hs[(size_t)e0.x * 32 + lane];
        uint2 x1 = g_hs[(size_t)e0.y * 32 + lane];
        uint2 x2 = g_hs[(size_t)e0.z * 32 + lane];
        uint2 x3 = g_hs[(size_t)e0.w * 32 + lane];
        uint2 x4 = g_hs[(size_t)e1.x * 32 + lane];
        uint2 x5 = g_hs[(size_t)e1.y * 32 + lane];
        uint2 x6 = g_hs[(size_t)e1.z * 32 + lane];
        uint2 x7 = g_hs[(size_t)e1.w * 32 + lane];
        // pairwise fp16 combine (one RNE rounding per element pair)
        __half2 p0l = __hadd2(*(__half2*)&x0.x, *(__half2*)&x1.x);
        __half2 p0h = __hadd2(*(__half2*)&x0.y, *(__half2*)&x1.y);
        __half2 p1l = __hadd2(*(__half2*)&x2.x, *(__half2*)&x3.x);
        __half2 p1h = __hadd2(*(__half2*)&x2.y, *(__half2*)&x3.y);
        __half2 p2l = __hadd2(*(__half2*)&x4.x, *(__half2*)&x5.x);
        __half2 p2h = __hadd2(*(__half2*)&x4.y, *(__half2*)&x5.y);
        __half2 p3l = __hadd2(*(__half2*)&x6.x, *(__half2*)&x7.x);
        __half2 p3h = __hadd2(*(__half2*)&x6.y, *(__half2*)&x7.y);
        float2 f;
        f = __half22float2(p0l); a0.x += f.x; a0.y += f.y;
        f = __half22float2(p0h); b0.x += f.x; b0.y += f.y;
        f = __half22float2(p1l); a1.x += f.x; a1.y += f.y;
        f = __half22float2(p1h); b1.x += f.x; b1.y += f.y;
        f = __half22float2(p2l); a0.x += f.x; a0.y += f.y;
        f = __half22float2(p2h); b0.x += f.x; b0.y += f.y;
        f = __half22float2(p3l); a1.x += f.x; a1.y += f.y;
        f = __half22float2(p3h); b1.x += f.x; b1.y += f.y;
    }
    for (; e < end; e++) {
        float4 f = unpack4h(g_hs[(size_t)g_esrc[e] * 32 + lane]);
        a0.x += f.x; a0.y += f.y; b0.x += f.z; b0.y += f.w;
    }
    float nd = g_ndst[v];
    float4 o;
    o.x = (a0.x + a1.x) * nd;
    o.y = (a0.y + a1.y) * nd;
    o.z = (b0.x + b1.x) * nd;
    o.w = (b0.y + b1.y) * nd;
    g_agg[v * 32 + lane] = pack4h(o);
}

// --------------------------- fp16 tensor-core GEMM -------------------------

constexpr int PADH = 136;                          // halves
constexpr int GEMM_SMEM = 2 * 128 * PADH * 2;      // 69632 B

template <bool TAIL>
__global__ void __launch_bounds__(256) k_gemm(int layer,
                                              const float* __restrict__ bia) {
    extern __shared__ __half smh[];
    __half* sA = smh;                    // [row][k]
    __half* sW = smh + 128 * PADH;       // [n][k]

    int tid  = threadIdx.x;
    int lane = tid & 31;
    int warp = tid >> 5;
    int row0 = blockIdx.x * 128;

    #pragma unroll
    for (int it = 0; it < 8; it++) {
        int i = it * 256 + tid;
        int r = i >> 4, c = i & 15;
        int gr = row0 + r;
        uint4 v = (gr < NN) ? *(const uint4*)&g_agg[(size_t)gr * 32 + c * 2]
                            : make_uint4(0u, 0u, 0u, 0u);
        *(uint4*)&sA[r * PADH + c * 8] = v;
    }
    const uint4* WT4 = (const uint4*)g_whT[layer];
    #pragma unroll
    for (int it = 0; it < 8; it++) {
        int i = it * 256 + tid;
        int n = i >> 4, c = i & 15;
        *(uint4*)&sW[n * PADH + c * 8] = WT4[i];
    }
    __syncthreads();

    int wm = (warp >> 1) * 32;
    int wn = (warp & 1) * 64;
    int qr = lane >> 2;
    int qc = lane & 3;

    float acc[2][8][4];
    #pragma unroll
    for (int mf = 0; mf < 2; mf++)
        #pragma unroll
        for (int nf = 0; nf < 8; nf++)
            #pragma unroll
            for (int j = 0; j < 4; j++) acc[mf][nf][j] = 0.f;

    #pragma unroll
    for (int ks = 0; ks < 8; ks++) {
        int kb = ks * 16;
        uint32_t a[2][4];
        #pragma unroll
        for (int mf = 0; mf < 2; mf++) {
            int r = wm + mf * 16 + qr;
            a[mf][0] = *(const uint32_t*)&sA[r * PADH + kb + qc * 2];
            a[mf][1] = *(const uint32_t*)&sA[(r + 8) * PADH + kb + qc * 2];
            a[mf][2] = *(const uint32_t*)&sA[r * PADH + kb + 8 + qc * 2];
            a[mf][3] = *(const uint32_t*)&sA[(r + 8) * PADH + kb + 8 + qc * 2];
        }
        #pragma unroll
        for (int nf = 0; nf < 8; nf++) {
            int n = wn + nf * 8 + qr;
            uint32_t b0 = *(const uint32_t*)&sW[n * PADH + kb + qc * 2];
            uint32_t b1 = *(const uint32_t*)&sW[n * PADH + kb + 8 + qc * 2];
            mma_f16(acc[0][nf], a[0], b0, b1);
            mma_f16(acc[1][nf], a[1], b0, b1);
        }
    }

    if (!TAIL) {
        #pragma unroll
        for (int mf = 0; mf < 2; mf++) {
            int r0 = row0 + wm + mf * 16 + qr;
            int r1 = r0 + 8;
            float s0 = (r0 < NN) ? g_nsrc[r0] : 0.f;
            float s1 = (r1 < NN) ? g_nsrc[r1] : 0.f;
            #pragma unroll
            for (int nf = 0; nf < 8; nf++) {
                int c = wn + nf * 8 + qc * 2;
                float2 bb = *(const float2*)&bia[c];
                if (r0 < NN) {
                    __half2 h = __floats2half2_rn(
                        fmaxf(acc[mf][nf][0] + bb.x, 0.f) * s0,
                        fmaxf(acc[mf][nf][1] + bb.y, 0.f) * s0);
                    ((__half2*)g_hs)[(size_t)r0 * 64 + (c >> 1)] = h;
                }
                if (r1 < NN) {
                    __half2 h = __floats2half2_rn(
                        fmaxf(acc[mf][nf][2] + bb.x, 0.f) * s1,
                        fmaxf(acc[mf][nf][3] + bb.y, 0.f) * s1);
                    ((__half2*)g_hs)[(size_t)r1 * 64 + (c >> 1)] = h;
                }
            }
        }
    } else {
        float* zred = (float*)smh;
        __syncthreads();
        if (tid < 256) zred[tid] = 0.f;
        __syncthreads();
        #pragma unroll
        for (int mf = 0; mf < 2; mf++) {
            int rl0 = wm + mf * 16 + qr;
            int rl1 = rl0 + 8;
            int r0 = row0 + rl0, r1 = row0 + rl1;
            float s0 = (r0 < NN) ? g_nsrc[r0] : 0.f;
            float s1 = (r1 < NN) ? g_nsrc[r1] : 0.f;
            float zl0 = 0.f, z2l0 = 0.f, zl1 = 0.f, z2l1 = 0.f;
            #pragma unroll
            for (int nf = 0; nf < 8; nf++) {
                int c = wn + nf * 8 + qc * 2;
                float2 bb  = *(const float2*)&bia[c];
                float2 qv  = *(const float2*)&g_q[c];
                float2 qv2 = *(const float2*)&g_q2[c];
                float h00 = fmaxf(acc[mf][nf][0] + bb.x, 0.f) * s0;
                float h01 = fmaxf(acc[mf][nf][1] + bb.y, 0.f) * s0;
                float h10 = fmaxf(acc[mf][nf][2] + bb.x, 0.f) * s1;
                float h11 = fmaxf(acc[mf][nf][3] + bb.y, 0.f) * s1;
                zl0  += h00 * qv.x  + h01 * qv.y;
                z2l0 += h00 * qv2.x + h01 * qv2.y;
                zl1  += h10 * qv.x  + h11 * qv.y;
                z2l1 += h10 * qv2.x + h11 * qv2.y;
            }
            atomicAdd(&zred[rl0 * 2],     zl0);
            atomicAdd(&zred[rl0 * 2 + 1], z2l0);
            atomicAdd(&zred[rl1 * 2],     zl1);
            atomicAdd(&zred[rl1 * 2 + 1], z2l1);
        }
        __syncthreads();
        if (tid < 128 && row0 + tid < NN)
            g_zz[row0 + tid] = make_float2(zred[tid * 2], zred[tid * 2 + 1]);
    }
}

// ---------------------- final edge pass + heads ----------------------------

__global__ void k_zagg(float* __restrict__ out) {
    __shared__ float red[256];
    int v = blockIdx.x * blockDim.x + threadIdx.x;
    float vp = 0.f;
    if (v < NN) {
        int beg = g_rowptr[v], end = g_rowptr[v + 1];
        float s0 = 0.f, s1 = 0.f, s2 = 0.f, s3 = 0.f;
        float t0 = 0.f, t1 = 0.f, t2 = 0.f, t3 = 0.f;
        int e = beg;
        for (; e + 3 < end; e += 4) {
            float2 a = g_zz[g_esrc[e]];
            float2 b = g_zz[g_esrc[e + 1]];
            float2 c = g_zz[g_esrc[e + 2]];
            float2 d = g_zz[g_esrc[e + 3]];
            s0 += a.x; t0 += a.y;
            s1 += b.x; t1 += b.y;
            s2 += c.x; t2 += c.y;
            s3 += d.x; t3 += d.y;
        }
        for (; e < end; e++) {
            float2 a = g_zz[g_esrc[e]];
            s0 += a.x; t0 += a.y;
        }
        float nd = g_ndst[v];
        out[v] = nd * ((s0 + s1) + (s2 + s3)) + g_cPI;
        vp = nd * ((t0 + t1) + (t2 + t3));
    }
    red[threadIdx.x] = vp;
    __syncthreads();
    for (int off = 128; off; off >>= 1) {
        if (threadIdx.x < off) red[threadIdx.x] += red[threadIdx.x + off];
        __syncthreads();
    }
    if (threadIdx.x == 0) atomicAdd(&out[NN], red[0]);
}

// --------------------------- launch ----------------------------------------

extern "C" void kernel_launch(void* const* d_in, const int* in_sizes, int n_in,
                              void* d_out, int out_size) {
    const float* feats = (const float*)d_in[0];
    const int*   src   = (const int*)d_in[1];
    const int*   dst   = (const int*)d_in[2];
    const float* W0 = (const float*)d_in[3];  const float* b0 = (const float*)d_in[4];
    const float* W1 = (const float*)d_in[5];  const float* b1 = (const float*)d_in[6];
    const float* W2 = (const float*)d_in[7];  const float* b2 = (const float*)d_in[8];
    const float* W3 = (const float*)d_in[9];  const float* b3 = (const float*)d_in[10];
    const float* Wp = (const float*)d_in[11]; const float* bp = (const float*)d_in[12];
    const float* Wv = (const float*)d_in[13]; const float* bv = (const float*)d_in[14];
    float* out = (float*)d_out;

    cudaFuncSetAttribute(k_gemm<false>, cudaFuncAttributeMaxDynamicSharedMemorySize,
                         GEMM_SMEM);
    cudaFuncSetAttribute(k_gemm<true>, cudaFuncAttributeMaxDynamicSharedMemorySize,
                         GEMM_SMEM);

    void* p_out_deg = nullptr;
    void* p_in_deg = nullptr;
    cudaGetSymbolAddress(&p_out_deg, g_outdeg);
    cudaGetSymbolAddress(&p_in_deg, g_indeg);
    cudaMemsetAsync(p_out_deg, 0, NN * sizeof(int));
    cudaMemsetAsync(p_in_deg, 0, NN * sizeof(int));

    k_histprep<<<HIST_BLOCKS + PREP_BLOCKS, 256>>>(
        src, dst, W0, W1, W2, W3, b3, Wp, bp, Wv, bv, out);
    k_scan<<<1, 1024>>>();
    k_fillnormscale<<<FILL_BLOCKS + NORM_BLOCKS + SC0_BLOCKS, 256>>>(src, dst, feats);

    const int aggGrid  = (NN + 7) / 8;        // 8 warps/block
    const int gemmGrid = (NN + 127) / 128;    // 391

    k_agg<<<aggGrid, 256>>>();
    k_gemm<false><<<gemmGrid, 256, GEMM_SMEM>>>(0, b0);
    k_agg<<<aggGrid, 256>>>();
    k_gemm<false><<<gemmGrid, 256, GEMM_SMEM>>>(1, b1);
    k_agg<<<aggGrid, 256>>>();
    k_gemm<true><<<gemmGrid, 256, GEMM_SMEM>>>(2, b2);

    k_zagg<<<(NN + 255) / 256, 256>>>(out);
}

// round 16
// speedup vs baseline: 1.6030x; 1.6030x over previous
#include <cuda_runtime.h>
#include <cuda_fp16.h>
#include <cstdint>

// ---------------------------------------------------------------------------
// GCN, 4 layers + heads. R16 = R14 base; single agg change vs R14:
// pairwise __hadd2 edge combine (fewer cvt/add ops). Scalar esrc index loads
// kept (R15's int4 indexing serialized the gather stream -> reverted).
// ---------------------------------------------------------------------------

constexpr int NN = 50000;
constexpr int NE = 800000;

__device__ int    g_outdeg[NN];
__device__ int    g_indeg[NN];
__device__ float  g_nsrc[NN];
__device__ float  g_ndst[NN];
__device__ int    g_rowptr[NN + 1];
__device__ int    g_cursor[NN];
__device__ int    g_esrc[NE];
__device__ uint2  g_hs[(size_t)NN * 32];    // fp16 activations (gather source)
__device__ uint2  g_agg[(size_t)NN * 32];   // fp16 aggregated * norm_dst (GEMM A)
__device__ __half g_whT[3][128 * 128];      // W0..W2 fp16 transposed [n][k]
__device__ float2 g_zz[NN];                 // (z, z2) per node
__device__ float  g_q[128];                 // W3 @ Wp
__device__ float  g_q2[128];                // W3 @ Wv
__device__ float  g_cPI;

__device__ __forceinline__ void mma_f16(float* c, const uint32_t* a,
                                        uint32_t b0, uint32_t b1) {
    asm("mma.sync.aligned.m16n8k16.row.col.f32.f16.f16.f32 "
        "{%0,%1,%2,%3},{%4,%5,%6,%7},{%8,%9},{%0,%1,%2,%3};"
        : "+f"(c[0]), "+f"(c[1]), "+f"(c[2]), "+f"(c[3])
        : "r"(a[0]), "r"(a[1]), "r"(a[2]), "r"(a[3]), "r"(b0), "r"(b1));
}

__device__ __forceinline__ uint2 pack4h(float4 v) {
    uint2 r;
    __half2 h0 = __floats2half2_rn(v.x, v.y);
    __half2 h1 = __floats2half2_rn(v.z, v.w);
    r.x = *(uint32_t*)&h0;
    r.y = *(uint32_t*)&h1;
    return r;
}
__device__ __forceinline__ float4 unpack4h(uint2 u) {
    __half2 h0 = *(__half2*)&u.x;
    __half2 h1 = *(__half2*)&u.y;
    float2 f0 = __half22float2(h0);
    float2 f1 = __half22float2(h1);
    return make_float4(f0.x, f0.y, f1.x, f1.y);
}

// --------------------------- setup ----------------------------------------

constexpr int HIST_BLOCKS = (NE + 255) / 256;       // 3125
constexpr int PREP_BLOCKS = 1 + 192;                // heads + W convert

__global__ void k_histprep(const int* __restrict__ src, const int* __restrict__ dst,
                           const float* __restrict__ W0, const float* __restrict__ W1,
                           const float* __restrict__ W2,
                           const float* __restrict__ W3, const float* __restrict__ b3,
                           const float* __restrict__ Wp, const float* __restrict__ bp,
                           const float* __restrict__ Wv, const float* __restrict__ bv,
                           float* __restrict__ out) {
    int gb = blockIdx.x;
    if (gb < HIST_BLOCKS) {
        int e = gb * 256 + threadIdx.x;
        if (e < NE) {
            atomicAdd(&g_outdeg[src[e]], 1);
            atomicAdd(&g_indeg[dst[e]], 1);
        }
    } else if (gb == HIST_BLOCKS) {
        int k = threadIdx.x;
        if (k < 128) {
            float a = 0.f, c = 0.f;
            for (int j = 0; j < 64; j++) {
                float w = W3[k * 64 + j];
                a += w * Wp[j];
                c += w * Wv[j];
            }
            g_q[k] = a;
            g_q2[k] = c;
            if (k == 0) {
                float cp = 0.f, cv = 0.f;
                for (int j = 0; j < 64; j++) { cp += b3[j] * Wp[j]; cv += b3[j] * Wv[j]; }
                g_cPI = cp + bp[0];
                out[NN] = (float)NN * cv + bv[0];
            }
        }
    } else {
        int idx = (gb - HIST_BLOCKS - 1) * 256 + threadIdx.x;   // 0 .. 3*16384-1
        if (idx < 3 * 16384) {
            int layer = idx >> 14;
            int rem = idx & 16383;
            int k = rem >> 7;
            int n = rem & 127;
            const float* W = (layer == 0) ? W0 : (layer == 1) ? W1 : W2;
            g_whT[layer][n * 128 + k] = __float2half(W[k * 128 + n]);
        }
    }
}

// Single-block scan only.
__global__ void k_scan() {
    constexpr int CH = (NN + 1023) / 1024;   // 49
    __shared__ int ts[1024];
    int t = threadIdx.x;
    int base = t * CH;
    int s = 0;
    for (int i = 0; i < CH; i++) {
        int idx = base + i;
        int v = (idx < NN) ? g_indeg[idx] : 0;
        if (idx < NN) g_rowptr[idx] = s;
        s += v;
    }
    ts[t] = s;
    __syncthreads();
    for (int off = 1; off < 1024; off <<= 1) {
        int v = (t >= off) ? ts[t - off] : 0;
        __syncthreads();
        ts[t] += v;
        __syncthreads();
    }
    int offset = ts[t] - s;
    for (int i = 0; i < CH; i++) {
        int idx = base + i;
        if (idx < NN) {
            int p = g_rowptr[idx] + offset;
            g_rowptr[idx] = p;
            g_cursor[idx] = p;
        }
    }
    if (t == 1023) g_rowptr[NN] = ts[1023];
}

constexpr int FILL_BLOCKS = (NE + 255) / 256;            // 3125
constexpr int NORM_BLOCKS = (NN + 255) / 256;            // 196
constexpr int SC0_BLOCKS  = (NN * 32 + 255) / 256;       // 6250

__global__ void k_fillnormscale(const int* __restrict__ src, const int* __restrict__ dst,
                                const float* __restrict__ feats) {
    int gb = blockIdx.x;
    if (gb < FILL_BLOCKS) {
        int e = gb * 256 + threadIdx.x;
        if (e < NE) {
            int p = atomicAdd(&g_cursor[dst[e]], 1);
            g_esrc[p] = src[e];
        }
    } else if (gb < FILL_BLOCKS + NORM_BLOCKS) {
        int j = (gb - FILL_BLOCKS) * 256 + threadIdx.x;
        if (j < NN) {
            g_nsrc[j] = rsqrtf((float)max(g_outdeg[j], 1));
            g_ndst[j] = rsqrtf((float)max(g_indeg[j], 1));
        }
    } else {
        int j = (gb - FILL_BLOCKS - NORM_BLOCKS) * 256 + threadIdx.x;  // uint2 idx
        if (j < NN * 32) {
            int node = j >> 5;
            float s = rsqrtf((float)max(g_outdeg[node], 1));
            float4 x = ((const float4*)feats)[j];
            x.x *= s; x.y *= s; x.z *= s; x.w *= s;
            g_hs[j] = pack4h(x);
        }
    }
}

// --------------------------- aggregation ----------------------------------
// One warp per node; lane owns 4 feats (8B fp16). 8-deep edge unroll with
// scalar index loads (keeps gather MLP); pairwise __hadd2 combine.

__global__ void k_agg() {
    int v = blockIdx.x * (blockDim.x >> 5) + (threadIdx.x >> 5);
    if (v >= NN) return;
    int lane = threadIdx.x & 31;
    int beg = g_rowptr[v], end = g_rowptr[v + 1];
    float2 a0 = make_float2(0.f, 0.f), a1 = make_float2(0.f, 0.f);
    float2 b0 = make_float2(0.f, 0.f), b1 = make_float2(0.f, 0.f);
    int e = beg;
    for (; e + 7 < end; e += 8) {
        uint2 x[8];
        #pragma unroll
        for (int j = 0; j < 8; j++)
            x[j] = g_hs[(size_t)g_esrc[e + j] * 32 + lane];
        // pairwise fp16 combine (one extra RNE rounding per element pair)
        __half2 p0l = __hadd2(*(__half2*)&x[0].x, *(__half2*)&x[1].x);
        __half2 p0h = __hadd2(*(__half2*)&x[0].y, *(__half2*)&x[1].y);
        __half2 p1l = __hadd2(*(__half2*)&x[2].x, *(__half2*)&x[3].x);
        __half2 p1h = __hadd2(*(__half2*)&x[2].y, *(__half2*)&x[3].y);
        __half2 p2l = __hadd2(*(__half2*)&x[4].x, *(__half2*)&x[5].x);
        __half2 p2h = __hadd2(*(__half2*)&x[4].y, *(__half2*)&x[5].y);
        __half2 p3l = __hadd2(*(__half2*)&x[6].x, *(__half2*)&x[7].x);
        __half2 p3h = __hadd2(*(__half2*)&x[6].y, *(__half2*)&x[7].y);
        float2 f;
        f = __half22float2(p0l); a0.x += f.x; a0.y += f.y;
        f = __half22float2(p0h); b0.x += f.x; b0.y += f.y;
        f = __half22float2(p1l); a1.x += f.x; a1.y += f.y;
        f = __half22float2(p1h); b1.x += f.x; b1.y += f.y;
        f = __half22float2(p2l); a0.x += f.x; a0.y += f.y;
        f = __half22float2(p2h); b0.x += f.x; b0.y += f.y;
        f = __half22float2(p3l); a1.x += f.x; a1.y += f.y;
        f = __half22float2(p3h); b1.x += f.x; b1.y += f.y;
    }
    for (; e < end; e++) {
        float4 f = unpack4h(g_hs[(size_t)g_esrc[e] * 32 + lane]);
        a0.x += f.x; a0.y += f.y; b0.x += f.z; b0.y += f.w;
    }
    float nd = g_ndst[v];
    float4 o;
    o.x = (a0.x + a1.x) * nd;
    o.y = (a0.y + a1.y) * nd;
    o.z = (b0.x + b1.x) * nd;
    o.w = (b0.y + b1.y) * nd;
    g_agg[v * 32 + lane] = pack4h(o);
}

// --------------------------- fp16 tensor-core GEMM -------------------------

constexpr int PADH = 136;                          // halves
constexpr int GEMM_SMEM = 2 * 128 * PADH * 2;      // 69632 B

template <bool TAIL>
__global__ void __launch_bounds__(256) k_gemm(int layer,
                                              const float* __restrict__ bia) {
    extern __shared__ __half smh[];
    __half* sA = smh;                    // [row][k]
    __half* sW = smh + 128 * PADH;       // [n][k]

    int tid  = threadIdx.x;
    int lane = tid & 31;
    int warp = tid >> 5;
    int row0 = blockIdx.x * 128;

    #pragma unroll
    for (int it = 0; it < 8; it++) {
        int i = it * 256 + tid;
        int r = i >> 4, c = i & 15;
        int gr = row0 + r;
        uint4 v = (gr < NN) ? *(const uint4*)&g_agg[(size_t)gr * 32 + c * 2]
                            : make_uint4(0u, 0u, 0u, 0u);
        *(uint4*)&sA[r * PADH + c * 8] = v;
    }
    const uint4* WT4 = (const uint4*)g_whT[layer];
    #pragma unroll
    for (int it = 0; it < 8; it++) {
        int i = it * 256 + tid;
        int n = i >> 4, c = i & 15;
        *(uint4*)&sW[n * PADH + c * 8] = WT4[i];
    }
    __syncthreads();

    int wm = (warp >> 1) * 32;
    int wn = (warp & 1) * 64;
    int qr = lane >> 2;
    int qc = lane & 3;

    float acc[2][8][4];
    #pragma unroll
    for (int mf = 0; mf < 2; mf++)
        #pragma unroll
        for (int nf = 0; nf < 8; nf++)
            #pragma unroll
            for (int j = 0; j < 4; j++) acc[mf][nf][j] = 0.f;

    #pragma unroll
    for (int ks = 0; ks < 8; ks++) {
        int kb = ks * 16;
        uint32_t a[2][4];
        #pragma unroll
        for (int mf = 0; mf < 2; mf++) {
            int r = wm + mf * 16 + qr;
            a[mf][0] = *(const uint32_t*)&sA[r * PADH + kb + qc * 2];
            a[mf][1] = *(const uint32_t*)&sA[(r + 8) * PADH + kb + qc * 2];
            a[mf][2] = *(const uint32_t*)&sA[r * PADH + kb + 8 + qc * 2];
            a[mf][3] = *(const uint32_t*)&sA[(r + 8) * PADH + kb + 8 + qc * 2];
        }
        #pragma unroll
        for (int nf = 0; nf < 8; nf++) {
            int n = wn + nf * 8 + qr;
            uint32_t b0 = *(const uint32_t*)&sW[n * PADH + kb + qc * 2];
            uint32_t b1 = *(const uint32_t*)&sW[n * PADH + kb + 8 + qc * 2];
            mma_f16(acc[0][nf], a[0], b0, b1);
            mma_f16(acc[1][nf], a[1], b0, b1);
        }
    }

    if (!TAIL) {
        #pragma unroll
        for (int mf = 0; mf < 2; mf++) {
            int r0 = row0 + wm + mf * 16 + qr;
            int r1 = r0 + 8;
            float s0 = (r0 < NN) ? g_nsrc[r0] : 0.f;
            float s1 = (r1 < NN) ? g_nsrc[r1] : 0.f;
            #pragma unroll
            for (int nf = 0; nf < 8; nf++) {
                int c = wn + nf * 8 + qc * 2;
                float2 bb = *(const float2*)&bia[c];
                if (r0 < NN) {
                    __half2 h = __floats2half2_rn(
                        fmaxf(acc[mf][nf][0] + bb.x, 0.f) * s0,
                        fmaxf(acc[mf][nf][1] + bb.y, 0.f) * s0);
                    ((__half2*)g_hs)[(size_t)r0 * 64 + (c >> 1)] = h;
                }
                if (r1 < NN) {
                    __half2 h = __floats2half2_rn(
                        fmaxf(acc[mf][nf][2] + bb.x, 0.f) * s1,
                        fmaxf(acc[mf][nf][3] + bb.y, 0.f) * s1);
                    ((__half2*)g_hs)[(size_t)r1 * 64 + (c >> 1)] = h;
                }
            }
        }
    } else {
        float* zred = (float*)smh;
        __syncthreads();
        if (tid < 256) zred[tid] = 0.f;
        __syncthreads();
        #pragma unroll
        for (int mf = 0; mf < 2; mf++) {
            int rl0 = wm + mf * 16 + qr;
            int rl1 = rl0 + 8;
            int r0 = row0 + rl0, r1 = row0 + rl1;
            float s0 = (r0 < NN) ? g_nsrc[r0] : 0.f;
            float s1 = (r1 < NN) ? g_nsrc[r1] : 0.f;
            float zl0 = 0.f, z2l0 = 0.f, zl1 = 0.f, z2l1 = 0.f;
            #pragma unroll
            for (int nf = 0; nf < 8; nf++) {
                int c = wn + nf * 8 + qc * 2;
                float2 bb  = *(const float2*)&bia[c];
                float2 qv  = *(const float2*)&g_q[c];
                float2 qv2 = *(const float2*)&g_q2[c];
                float h00 = fmaxf(acc[mf][nf][0] + bb.x, 0.f) * s0;
                float h01 = fmaxf(acc[mf][nf][1] + bb.y, 0.f) * s0;
                float h10 = fmaxf(acc[mf][nf][2] + bb.x, 0.f) * s1;
                float h11 = fmaxf(acc[mf][nf][3] + bb.y, 0.f) * s1;
                zl0  += h00 * qv.x  + h01 * qv.y;
                z2l0 += h00 * qv2.x + h01 * qv2.y;
                zl1  += h10 * qv.x  + h11 * qv.y;
                z2l1 += h10 * qv2.x + h11 * qv2.y;
            }
            atomicAdd(&zred[rl0 * 2],     zl0);
            atomicAdd(&zred[rl0 * 2 + 1], z2l0);
            atomicAdd(&zred[rl1 * 2],     zl1);
            atomicAdd(&zred[rl1 * 2 + 1], z2l1);
        }
        __syncthreads();
        if (tid < 128 && row0 + tid < NN)
            g_zz[row0 + tid] = make_float2(zred[tid * 2], zred[tid * 2 + 1]);
    }
}

// ---------------------- final edge pass + heads ----------------------------

__global__ void k_zagg(float* __restrict__ out) {
    __shared__ float red[256];
    int v = blockIdx.x * blockDim.x + threadIdx.x;
    float vp = 0.f;
    if (v < NN) {
        int beg = g_rowptr[v], end = g_rowptr[v + 1];
        float s0 = 0.f, s1 = 0.f, s2 = 0.f, s3 = 0.f;
        float t0 = 0.f, t1 = 0.f, t2 = 0.f, t3 = 0.f;
        int e = beg;
        for (; e + 3 < end; e += 4) {
            float2 a = g_zz[g_esrc[e]];
            float2 b = g_zz[g_esrc[e + 1]];
            float2 c = g_zz[g_esrc[e + 2]];
            float2 d = g_zz[g_esrc[e + 3]];
            s0 += a.x; t0 += a.y;
            s1 += b.x; t1 += b.y;
            s2 += c.x; t2 += c.y;
            s3 += d.x; t3 += d.y;
        }
        for (; e < end; e++) {
            float2 a = g_zz[g_esrc[e]];
            s0 += a.x; t0 += a.y;
        }
        float nd = g_ndst[v];
        out[v] = nd * ((s0 + s1) + (s2 + s3)) + g_cPI;
        vp = nd * ((t0 + t1) + (t2 + t3));
    }
    red[threadIdx.x] = vp;
    __syncthreads();
    for (int off = 128; off; off >>= 1) {
        if (threadIdx.x < off) red[threadIdx.x] += red[threadIdx.x + off];
        __syncthreads();
    }
    if (threadIdx.x == 0) atomicAdd(&out[NN], red[0]);
}

// --------------------------- launch ----------------------------------------

extern "C" void kernel_launch(void* const* d_in, const int* in_sizes, int n_in,
                              void* d_out, int out_size) {
    const float* feats = (const float*)d_in[0];
    const int*   src   = (const int*)d_in[1];
    const int*   dst   = (const int*)d_in[2];
    const float* W0 = (const float*)d_in[3];  const float* b0 = (const float*)d_in[4];
    const float* W1 = (const float*)d_in[5];  const float* b1 = (const float*)d_in[6];
    const float* W2 = (const float*)d_in[7];  const float* b2 = (const float*)d_in[8];
    const float* W3 = (const float*)d_in[9];  const float* b3 = (const float*)d_in[10];
    const float* Wp = (const float*)d_in[11]; const float* bp = (const float*)d_in[12];
    const float* Wv = (const float*)d_in[13]; const float* bv = (const float*)d_in[14];
    float* out = (float*)d_out;

    cudaFuncSetAttribute(k_gemm<false>, cudaFuncAttributeMaxDynamicSharedMemorySize,
                         GEMM_SMEM);
    cudaFuncSetAttribute(k_gemm<true>, cudaFuncAttributeMaxDynamicSharedMemorySize,
                         GEMM_SMEM);

    void* p_out_deg = nullptr;
    void* p_in_deg = nullptr;
    cudaGetSymbolAddress(&p_out_deg, g_outdeg);
    cudaGetSymbolAddress(&p_in_deg, g_indeg);
    cudaMemsetAsync(p_out_deg, 0, NN * sizeof(int));
    cudaMemsetAsync(p_in_deg, 0, NN * sizeof(int));

    k_histprep<<<HIST_BLOCKS + PREP_BLOCKS, 256>>>(
        src, dst, W0, W1, W2, W3, b3, Wp, bp, Wv, bv, out);
    k_scan<<<1, 1024>>>();
    k_fillnormscale<<<FILL_BLOCKS + NORM_BLOCKS + SC0_BLOCKS, 256>>>(src, dst, feats);

    const int aggGrid  = (NN + 7) / 8;        // 8 warps/block
    const int gemmGrid = (NN + 127) / 128;    // 391

    k_agg<<<aggGrid, 256>>>();
    k_gemm<false><<<gemmGrid, 256, GEMM_SMEM>>>(0, b0);
    k_agg<<<aggGrid, 256>>>();
    k_gemm<false><<<gemmGrid, 256, GEMM_SMEM>>>(1, b1);
    k_agg<<<aggGrid, 256>>>();
    k_gemm<true><<<gemmGrid, 256, GEMM_SMEM>>>(2, b2);

    k_zagg<<<(NN + 255) / 256, 256>>>(out);
}

// round 17
// speedup vs baseline: 1.6165x; 1.0084x over previous
#include <cuda_runtime.h>
#include <cuda_fp16.h>
#include <cstdint>

// ---------------------------------------------------------------------------
// GCN, 4 layers + heads. R17 = R16 + two-level __hadd2 tree in agg
// (widen to fp32 once per 4 edges) + 8-wide unroll in zagg.
// ---------------------------------------------------------------------------

constexpr int NN = 50000;
constexpr int NE = 800000;

__device__ int    g_outdeg[NN];
__device__ int    g_indeg[NN];
__device__ float  g_nsrc[NN];
__device__ float  g_ndst[NN];
__device__ int    g_rowptr[NN + 1];
__device__ int    g_cursor[NN];
__device__ int    g_esrc[NE];
__device__ uint2  g_hs[(size_t)NN * 32];    // fp16 activations (gather source)
__device__ uint2  g_agg[(size_t)NN * 32];   // fp16 aggregated * norm_dst (GEMM A)
__device__ __half g_whT[3][128 * 128];      // W0..W2 fp16 transposed [n][k]
__device__ float2 g_zz[NN];                 // (z, z2) per node
__device__ float  g_q[128];                 // W3 @ Wp
__device__ float  g_q2[128];                // W3 @ Wv
__device__ float  g_cPI;

__device__ __forceinline__ void mma_f16(float* c, const uint32_t* a,
                                        uint32_t b0, uint32_t b1) {
    asm("mma.sync.aligned.m16n8k16.row.col.f32.f16.f16.f32 "
        "{%0,%1,%2,%3},{%4,%5,%6,%7},{%8,%9},{%0,%1,%2,%3};"
        : "+f"(c[0]), "+f"(c[1]), "+f"(c[2]), "+f"(c[3])
        : "r"(a[0]), "r"(a[1]), "r"(a[2]), "r"(a[3]), "r"(b0), "r"(b1));
}

__device__ __forceinline__ uint2 pack4h(float4 v) {
    uint2 r;
    __half2 h0 = __floats2half2_rn(v.x, v.y);
    __half2 h1 = __floats2half2_rn(v.z, v.w);
    r.x = *(uint32_t*)&h0;
    r.y = *(uint32_t*)&h1;
    return r;
}
__device__ __forceinline__ float4 unpack4h(uint2 u) {
    __half2 h0 = *(__half2*)&u.x;
    __half2 h1 = *(__half2*)&u.y;
    float2 f0 = __half22float2(h0);
    float2 f1 = __half22float2(h1);
    return make_float4(f0.x, f0.y, f1.x, f1.y);
}

// --------------------------- setup ----------------------------------------

constexpr int HIST_BLOCKS = (NE + 255) / 256;       // 3125
constexpr int PREP_BLOCKS = 1 + 192;                // heads + W convert

__global__ void k_histprep(const int* __restrict__ src, const int* __restrict__ dst,
                           const float* __restrict__ W0, const float* __restrict__ W1,
                           const float* __restrict__ W2,
                           const float* __restrict__ W3, const float* __restrict__ b3,
                           const float* __restrict__ Wp, const float* __restrict__ bp,
                           const float* __restrict__ Wv, const float* __restrict__ bv,
                           float* __restrict__ out) {
    int gb = blockIdx.x;
    if (gb < HIST_BLOCKS) {
        int e = gb * 256 + threadIdx.x;
        if (e < NE) {
            atomicAdd(&g_outdeg[src[e]], 1);
            atomicAdd(&g_indeg[dst[e]], 1);
        }
    } else if (gb == HIST_BLOCKS) {
        int k = threadIdx.x;
        if (k < 128) {
            float a = 0.f, c = 0.f;
            for (int j = 0; j < 64; j++) {
                float w = W3[k * 64 + j];
                a += w * Wp[j];
                c += w * Wv[j];
            }
            g_q[k] = a;
            g_q2[k] = c;
            if (k == 0) {
                float cp = 0.f, cv = 0.f;
                for (int j = 0; j < 64; j++) { cp += b3[j] * Wp[j]; cv += b3[j] * Wv[j]; }
                g_cPI = cp + bp[0];
                out[NN] = (float)NN * cv + bv[0];
            }
        }
    } else {
        int idx = (gb - HIST_BLOCKS - 1) * 256 + threadIdx.x;   // 0 .. 3*16384-1
        if (idx < 3 * 16384) {
            int layer = idx >> 14;
            int rem = idx & 16383;
            int k = rem >> 7;
            int n = rem & 127;
            const float* W = (layer == 0) ? W0 : (layer == 1) ? W1 : W2;
            g_whT[layer][n * 128 + k] = __float2half(W[k * 128 + n]);
        }
    }
}

// Single-block scan only.
__global__ void k_scan() {
    constexpr int CH = (NN + 1023) / 1024;   // 49
    __shared__ int ts[1024];
    int t = threadIdx.x;
    int base = t * CH;
    int s = 0;
    for (int i = 0; i < CH; i++) {
        int idx = base + i;
        int v = (idx < NN) ? g_indeg[idx] : 0;
        if (idx < NN) g_rowptr[idx] = s;
        s += v;
    }
    ts[t] = s;
    __syncthreads();
    for (int off = 1; off < 1024; off <<= 1) {
        int v = (t >= off) ? ts[t - off] : 0;
        __syncthreads();
        ts[t] += v;
        __syncthreads();
    }
    int offset = ts[t] - s;
    for (int i = 0; i < CH; i++) {
        int idx = base + i;
        if (idx < NN) {
            int p = g_rowptr[idx] + offset;
            g_rowptr[idx] = p;
            g_cursor[idx] = p;
        }
    }
    if (t == 1023) g_rowptr[NN] = ts[1023];
}

constexpr int FILL_BLOCKS = (NE + 255) / 256;            // 3125
constexpr int NORM_BLOCKS = (NN + 255) / 256;            // 196
constexpr int SC0_BLOCKS  = (NN * 32 + 255) / 256;       // 6250

__global__ void k_fillnormscale(const int* __restrict__ src, const int* __restrict__ dst,
                                const float* __restrict__ feats) {
    int gb = blockIdx.x;
    if (gb < FILL_BLOCKS) {
        int e = gb * 256 + threadIdx.x;
        if (e < NE) {
            int p = atomicAdd(&g_cursor[dst[e]], 1);
            g_esrc[p] = src[e];
        }
    } else if (gb < FILL_BLOCKS + NORM_BLOCKS) {
        int j = (gb - FILL_BLOCKS) * 256 + threadIdx.x;
        if (j < NN) {
            g_nsrc[j] = rsqrtf((float)max(g_outdeg[j], 1));
            g_ndst[j] = rsqrtf((float)max(g_indeg[j], 1));
        }
    } else {
        int j = (gb - FILL_BLOCKS - NORM_BLOCKS) * 256 + threadIdx.x;  // uint2 idx
        if (j < NN * 32) {
            int node = j >> 5;
            float s = rsqrtf((float)max(g_outdeg[node], 1));
            float4 x = ((const float4*)feats)[j];
            x.x *= s; x.y *= s; x.z *= s; x.w *= s;
            g_hs[j] = pack4h(x);
        }
    }
}

// --------------------------- aggregation ----------------------------------
// One warp per node; lane owns 4 feats (8B fp16). 8-deep edge unroll, scalar
// index loads (MLP preserved); two-level __hadd2 tree, widen per 4 edges.

__global__ void k_agg() {
    int v = blockIdx.x * (blockDim.x >> 5) + (threadIdx.x >> 5);
    if (v >= NN) return;
    int lane = threadIdx.x & 31;
    int beg = g_rowptr[v], end = g_rowptr[v + 1];
    float2 a0 = make_float2(0.f, 0.f), a1 = make_float2(0.f, 0.f);
    float2 b0 = make_float2(0.f, 0.f), b1 = make_float2(0.f, 0.f);
    int e = beg;
    for (; e + 7 < end; e += 8) {
        uint2 x[8];
        #pragma unroll
        for (int j = 0; j < 8; j++)
            x[j] = g_hs[(size_t)g_esrc[e + j] * 32 + lane];
        // level 1: pairs
        __half2 p0l = __hadd2(*(__half2*)&x[0].x, *(__half2*)&x[1].x);
        __half2 p0h = __hadd2(*(__half2*)&x[0].y, *(__half2*)&x[1].y);
        __half2 p1l = __hadd2(*(__half2*)&x[2].x, *(__half2*)&x[3].x);
        __half2 p1h = __hadd2(*(__half2*)&x[2].y, *(__half2*)&x[3].y);
        __half2 p2l = __hadd2(*(__half2*)&x[4].x, *(__half2*)&x[5].x);
        __half2 p2h = __hadd2(*(__half2*)&x[4].y, *(__half2*)&x[5].y);
        __half2 p3l = __hadd2(*(__half2*)&x[6].x, *(__half2*)&x[7].x);
        __half2 p3h = __hadd2(*(__half2*)&x[6].y, *(__half2*)&x[7].y);
        // level 2: pairs of pairs
        __half2 q0l = __hadd2(p0l, p1l);
        __half2 q0h = __hadd2(p0h, p1h);
        __half2 q1l = __hadd2(p2l, p3l);
        __half2 q1h = __hadd2(p2h, p3h);
        float2 f;
        f = __half22float2(q0l); a0.x += f.x; a0.y += f.y;
        f = __half22float2(q0h); b0.x += f.x; b0.y += f.y;
        f = __half22float2(q1l); a1.x += f.x; a1.y += f.y;
        f = __half22float2(q1h); b1.x += f.x; b1.y += f.y;
    }
    for (; e < end; e++) {
        float4 f = unpack4h(g_hs[(size_t)g_esrc[e] * 32 + lane]);
        a0.x += f.x; a0.y += f.y; b0.x += f.z; b0.y += f.w;
    }
    float nd = g_ndst[v];
    float4 o;
    o.x = (a0.x + a1.x) * nd;
    o.y = (a0.y + a1.y) * nd;
    o.z = (b0.x + b1.x) * nd;
    o.w = (b0.y + b1.y) * nd;
    g_agg[v * 32 + lane] = pack4h(o);
}

// --------------------------- fp16 tensor-core GEMM -------------------------

constexpr int PADH = 136;                          // halves
constexpr int GEMM_SMEM = 2 * 128 * PADH * 2;      // 69632 B

template <bool TAIL>
__global__ void __launch_bounds__(256) k_gemm(int layer,
                                              const float* __restrict__ bia) {
    extern __shared__ __half smh[];
    __half* sA = smh;                    // [row][k]
    __half* sW = smh + 128 * PADH;       // [n][k]

    int tid  = threadIdx.x;
    int lane = tid & 31;
    int warp = tid >> 5;
    int row0 = blockIdx.x * 128;

    #pragma unroll
    for (int it = 0; it < 8; it++) {
        int i = it * 256 + tid;
        int r = i >> 4, c = i & 15;
        int gr = row0 + r;
        uint4 v = (gr < NN) ? *(const uint4*)&g_agg[(size_t)gr * 32 + c * 2]
                            : make_uint4(0u, 0u, 0u, 0u);
        *(uint4*)&sA[r * PADH + c * 8] = v;
    }
    const uint4* WT4 = (const uint4*)g_whT[layer];
    #pragma unroll
    for (int it = 0; it < 8; it++) {
        int i = it * 256 + tid;
        int n = i >> 4, c = i & 15;
        *(uint4*)&sW[n * PADH + c * 8] = WT4[i];
    }
    __syncthreads();

    int wm = (warp >> 1) * 32;
    int wn = (warp & 1) * 64;
    int qr = lane >> 2;
    int qc = lane & 3;

    float acc[2][8][4];
    #pragma unroll
    for (int mf = 0; mf < 2; mf++)
        #pragma unroll
        for (int nf = 0; nf < 8; nf++)
            #pragma unroll
            for (int j = 0; j < 4; j++) acc[mf][nf][j] = 0.f;

    #pragma unroll
    for (int ks = 0; ks < 8; ks++) {
        int kb = ks * 16;
        uint32_t a[2][4];
        #pragma unroll
        for (int mf = 0; mf < 2; mf++) {
            int r = wm + mf * 16 + qr;
            a[mf][0] = *(const uint32_t*)&sA[r * PADH + kb + qc * 2];
            a[mf][1] = *(const uint32_t*)&sA[(r + 8) * PADH + kb + qc * 2];
            a[mf][2] = *(const uint32_t*)&sA[r * PADH + kb + 8 + qc * 2];
            a[mf][3] = *(const uint32_t*)&sA[(r + 8) * PADH + kb + 8 + qc * 2];
        }
        #pragma unroll
        for (int nf = 0; nf < 8; nf++) {
            int n = wn + nf * 8 + qr;
            uint32_t b0 = *(const uint32_t*)&sW[n * PADH + kb + qc * 2];
            uint32_t b1 = *(const uint32_t*)&sW[n * PADH + kb + 8 + qc * 2];
            mma_f16(acc[0][nf], a[0], b0, b1);
            mma_f16(acc[1][nf], a[1], b0, b1);
        }
    }

    if (!TAIL) {
        #pragma unroll
        for (int mf = 0; mf < 2; mf++) {
            int r0 = row0 + wm + mf * 16 + qr;
            int r1 = r0 + 8;
            float s0 = (r0 < NN) ? g_nsrc[r0] : 0.f;
            float s1 = (r1 < NN) ? g_nsrc[r1] : 0.f;
            #pragma unroll
            for (int nf = 0; nf < 8; nf++) {
                int c = wn + nf * 8 + qc * 2;
                float2 bb = *(const float2*)&bia[c];
                if (r0 < NN) {
                    __half2 h = __floats2half2_rn(
                        fmaxf(acc[mf][nf][0] + bb.x, 0.f) * s0,
                        fmaxf(acc[mf][nf][1] + bb.y, 0.f) * s0);
                    ((__half2*)g_hs)[(size_t)r0 * 64 + (c >> 1)] = h;
                }
                if (r1 < NN) {
                    __half2 h = __floats2half2_rn(
                        fmaxf(acc[mf][nf][2] + bb.x, 0.f) * s1,
                        fmaxf(acc[mf][nf][3] + bb.y, 0.f) * s1);
                    ((__half2*)g_hs)[(size_t)r1 * 64 + (c >> 1)] = h;
                }
            }
        }
    } else {
        float* zred = (float*)smh;
        __syncthreads();
        if (tid < 256) zred[tid] = 0.f;
        __syncthreads();
        #pragma unroll
        for (int mf = 0; mf < 2; mf++) {
            int rl0 = wm + mf * 16 + qr;
            int rl1 = rl0 + 8;
            int r0 = row0 + rl0, r1 = row0 + rl1;
            float s0 = (r0 < NN) ? g_nsrc[r0] : 0.f;
            float s1 = (r1 < NN) ? g_nsrc[r1] : 0.f;
            float zl0 = 0.f, z2l0 = 0.f, zl1 = 0.f, z2l1 = 0.f;
            #pragma unroll
            for (int nf = 0; nf < 8; nf++) {
                int c = wn + nf * 8 + qc * 2;
                float2 bb  = *(const float2*)&bia[c];
                float2 qv  = *(const float2*)&g_q[c];
                float2 qv2 = *(const float2*)&g_q2[c];
                float h00 = fmaxf(acc[mf][nf][0] + bb.x, 0.f) * s0;
                float h01 = fmaxf(acc[mf][nf][1] + bb.y, 0.f) * s0;
                float h10 = fmaxf(acc[mf][nf][2] + bb.x, 0.f) * s1;
                float h11 = fmaxf(acc[mf][nf][3] + bb.y, 0.f) * s1;
                zl0  += h00 * qv.x  + h01 * qv.y;
                z2l0 += h00 * qv2.x + h01 * qv2.y;
                zl1  += h10 * qv.x  + h11 * qv.y;
                z2l1 += h10 * qv2.x + h11 * qv2.y;
            }
            atomicAdd(&zred[rl0 * 2],     zl0);
            atomicAdd(&zred[rl0 * 2 + 1], z2l0);
            atomicAdd(&zred[rl1 * 2],     zl1);
            atomicAdd(&zred[rl1 * 2 + 1], z2l1);
        }
        __syncthreads();
        if (tid < 128 && row0 + tid < NN)
            g_zz[row0 + tid] = make_float2(zred[tid * 2], zred[tid * 2 + 1]);
    }
}

// ---------------------- final edge pass + heads ----------------------------

__global__ void k_zagg(float* __restrict__ out) {
    __shared__ float red[256];
    int v = blockIdx.x * blockDim.x + threadIdx.x;
    float vp = 0.f;
    if (v < NN) {
        int beg = g_rowptr[v], end = g_rowptr[v + 1];
        float s0 = 0.f, s1 = 0.f, s2 = 0.f, s3 = 0.f;
        float t0 = 0.f, t1 = 0.f, t2 = 0.f, t3 = 0.f;
        int e = beg;
        for (; e + 7 < end; e += 8) {
            float2 z0 = g_zz[g_esrc[e]];
            float2 z1 = g_zz[g_esrc[e + 1]];
            float2 z2 = g_zz[g_esrc[e + 2]];
            float2 z3 = g_zz[g_esrc[e + 3]];
            float2 z4 = g_zz[g_esrc[e + 4]];
            float2 z5 = g_zz[g_esrc[e + 5]];
            float2 z6 = g_zz[g_esrc[e + 6]];
            float2 z7 = g_zz[g_esrc[e + 7]];
            s0 += z0.x; t0 += z0.y;
            s1 += z1.x; t1 += z1.y;
            s2 += z2.x; t2 += z2.y;
            s3 += z3.x; t3 += z3.y;
            s0 += z4.x; t0 += z4.y;
            s1 += z5.x; t1 += z5.y;
            s2 += z6.x; t2 += z6.y;
            s3 += z7.x; t3 += z7.y;
        }
        for (; e < end; e++) {
            float2 a = g_zz[g_esrc[e]];
            s0 += a.x; t0 += a.y;
        }
        float nd = g_ndst[v];
        out[v] = nd * ((s0 + s1) + (s2 + s3)) + g_cPI;
        vp = nd * ((t0 + t1) + (t2 + t3));
    }
    red[threadIdx.x] = vp;
    __syncthreads();
    for (int off = 128; off; off >>= 1) {
        if (threadIdx.x < off) red[threadIdx.x] += red[threadIdx.x + off];
        __syncthreads();
    }
    if (threadIdx.x == 0) atomicAdd(&out[NN], red[0]);
}

// --------------------------- launch ----------------------------------------

extern "C" void kernel_launch(void* const* d_in, const int* in_sizes, int n_in,
                              void* d_out, int out_size) {
    const float* feats = (const float*)d_in[0];
    const int*   src   = (const int*)d_in[1];
    const int*   dst   = (const int*)d_in[2];
    const float* W0 = (const float*)d_in[3];  const float* b0 = (const float*)d_in[4];
    const float* W1 = (const float*)d_in[5];  const float* b1 = (const float*)d_in[6];
    const float* W2 = (const float*)d_in[7];  const float* b2 = (const float*)d_in[8];
    const float* W3 = (const float*)d_in[9];  const float* b3 = (const float*)d_in[10];
    const float* Wp = (const float*)d_in[11]; const float* bp = (const float*)d_in[12];
    const float* Wv = (const float*)d_in[13]; const float* bv = (const float*)d_in[14];
    float* out = (float*)d_out;

    cudaFuncSetAttribute(k_gemm<false>, cudaFuncAttributeMaxDynamicSharedMemorySize,
                         GEMM_SMEM);
    cudaFuncSetAttribute(k_gemm<true>, cudaFuncAttributeMaxDynamicSharedMemorySize,
                         GEMM_SMEM);

    void* p_out_deg = nullptr;
    void* p_in_deg = nullptr;
    cudaGetSymbolAddress(&p_out_deg, g_outdeg);
    cudaGetSymbolAddress(&p_in_deg, g_indeg);
    cudaMemsetAsync(p_out_deg, 0, NN * sizeof(int));
    cudaMemsetAsync(p_in_deg, 0, NN * sizeof(int));

    k_histprep<<<HIST_BLOCKS + PREP_BLOCKS, 256>>>(
        src, dst, W0, W1, W2, W3, b3, Wp, bp, Wv, bv, out);
    k_scan<<<1, 1024>>>();
    k_fillnormscale<<<FILL_BLOCKS + NORM_BLOCKS + SC0_BLOCKS, 256>>>(src, dst, feats);

    const int aggGrid  = (NN + 7) / 8;        // 8 warps/block
    const int gemmGrid = (NN + 127) / 128;    // 391

    k_agg<<<aggGrid, 256>>>();
    k_gemm<false><<<gemmGrid, 256, GEMM_SMEM>>>(0, b0);
    k_agg<<<aggGrid, 256>>>();
    k_gemm<false><<<gemmGrid, 256, GEMM_SMEM>>>(1, b1);
    k_agg<<<aggGrid, 256>>>();
    k_gemm<true><<<gemmGrid, 256, GEMM_SMEM>>>(2, b2);

    k_zagg<<<(NN + 255) / 256, 256>>>(out);
}